// round 13
// baseline (speedup 1.0000x reference)
#include <cuda_runtime.h>
#include <cuda_fp16.h>
#include <cstdint>

#define IDIM 1024
#define ODIM 1024
#define NDEG 9
#define KG 8192            // GEMM K (Chebyshev j = 1..8); T0 handled as bias
#define BMAX 8192

// ---------------- device scratch (static globals: allocation-guard safe) ----
__device__ __half g_A[(size_t)BMAX * KG];   // T basis fp16, k = (j-1)*1024 + i
__device__ __half g_B[(size_t)ODIM * KG];   // coeffs fp16,  [o][k]
__device__ float g_bias[ODIM];

// ---------------------------------------------------------------------------
// Kernel 1: fused row min/max + Chebyshev basis -> fp16
// ---------------------------------------------------------------------------
__global__ void __launch_bounds__(256) buildT_kernel(const float* __restrict__ x) {
    const int b = blockIdx.x;
    const int tid = threadIdx.x;
    const float* row = x + (size_t)b * IDIM;

    float2 v[2];
    #pragma unroll
    for (int s = 0; s < 2; s++)
        v[s] = *(const float2*)(row + 2 * (tid + 256 * s));

    float mn = fminf(fminf(v[0].x, v[0].y), fminf(v[1].x, v[1].y));
    float mx = fmaxf(fmaxf(v[0].x, v[0].y), fmaxf(v[1].x, v[1].y));
    #pragma unroll
    for (int o = 16; o; o >>= 1) {
        mn = fminf(mn, __shfl_xor_sync(0xFFFFFFFFu, mn, o));
        mx = fmaxf(mx, __shfl_xor_sync(0xFFFFFFFFu, mx, o));
    }
    __shared__ float smn[8], smx[8];
    int w = tid >> 5, l = tid & 31;
    if (l == 0) { smn[w] = mn; smx[w] = mx; }
    __syncthreads();
    #pragma unroll
    for (int i = 0; i < 8; i++) { mn = fminf(mn, smn[i]); mx = fmaxf(mx, smx[i]); }
    const float sc = 2.0f / (mx - mn);

    const size_t base = (size_t)b * KG;
    #pragma unroll
    for (int s = 0; s < 2; s++) {
        int p = tid + 256 * s;
        float xa = (v[s].x - mn) * sc - 1.0f;
        float xb = (v[s].y - mn) * sc - 1.0f;
        float a0 = 1.0f, a1 = xa, b0 = 1.0f, b1 = xb;
        #pragma unroll
        for (int j = 1; j < NDEG; j++) {
            __half2 h2;
            h2.x = __float2half_rn(a1);
            h2.y = __float2half_rn(b1);
            *(__half2*)(g_A + base + (size_t)(j - 1) * IDIM + 2 * p) = h2;
            float na = 2.0f * xa * a1 - a0; a0 = a1; a1 = na;
            float nb = 2.0f * xb * b1 - b0; b0 = b1; b1 = nb;
        }
    }
}

// ---------------------------------------------------------------------------
// Kernel 2: coeffs [i][o][j] -> B[o][k=(j-1)*1024+i] fp16
// ---------------------------------------------------------------------------
__global__ void transC_kernel(const float* __restrict__ c) {
    int idx = blockIdx.x * blockDim.x + threadIdx.x;
    if (idx >= ODIM * (IDIM / 2)) return;
    int o = idx >> 9;
    int p = idx & 511;
    const float* s0 = c + ((size_t)(2 * p) * ODIM + o) * NDEG;
    const float* s1 = c + ((size_t)(2 * p + 1) * ODIM + o) * NDEG;
    size_t base = (size_t)o * KG + 2 * p;
    #pragma unroll
    for (int j = 1; j < NDEG; j++) {
        __half2 h2;
        h2.x = __float2half_rn(s0[j]);
        h2.y = __float2half_rn(s1[j]);
        *(__half2*)(g_B + base + (size_t)(j - 1) * IDIM) = h2;
    }
}

// ---------------------------------------------------------------------------
// Kernel 3: bias[o] = sum_i c[i][o][0]
// ---------------------------------------------------------------------------
__global__ void __launch_bounds__(256) bias_kernel(const float* __restrict__ c) {
    const int o = blockIdx.x;
    float s = 0.0f;
    for (int i = threadIdx.x; i < IDIM; i += 256)
        s += c[((size_t)i * ODIM + o) * NDEG];
    #pragma unroll
    for (int w = 16; w; w >>= 1) s += __shfl_xor_sync(0xFFFFFFFFu, s, w);
    __shared__ float sh[8];
    if ((threadIdx.x & 31) == 0) sh[threadIdx.x >> 5] = s;
    __syncthreads();
    if (threadIdx.x == 0) {
        float t = 0.0f;
        #pragma unroll
        for (int i = 0; i < 8; i++) t += sh[i];
        g_bias[o] = t;
    }
}

// ---------------------------------------------------------------------------
// Kernel 4: fp16 GEMM, CTA 128x256, 256 thr, warp 64x64, 3-stage ring
// ---------------------------------------------------------------------------
#define TILE_M 128
#define TILE_N 256
#define NQG (KG / 64)               // 128 stages of 64 elems
#define ROWPB 144
#define A_ST (TILE_M * ROWPB)       // 18432
#define B_ST (TILE_N * ROWPB)       // 36864
#define STAGE (A_ST + B_ST)         // 55296
#define SMEM_TOTAL (3 * STAGE)      // 165888

__device__ __forceinline__ uint32_t smem_u32(const void* p) {
    uint32_t a;
    asm("{ .reg .u64 t; cvta.to.shared.u64 t, %1; cvt.u32.u64 %0, t; }"
        : "=r"(a) : "l"(p));
    return a;
}
__device__ __forceinline__ void cp16(uint32_t dst, const void* src) {
    asm volatile("cp.async.cg.shared.global [%0], [%1], 16;" :: "r"(dst), "l"(src));
}
__device__ __forceinline__ void ldmx4(uint32_t* r, uint32_t addr) {
    asm volatile("ldmatrix.sync.aligned.m8n8.x4.shared.b16 {%0,%1,%2,%3}, [%4];"
                 : "=r"(r[0]), "=r"(r[1]), "=r"(r[2]), "=r"(r[3]) : "r"(addr));
}
__device__ __forceinline__ void mma_f16(float* c, const uint32_t* a, const uint32_t* b) {
    asm volatile(
        "mma.sync.aligned.m16n8k16.row.col.f32.f16.f16.f32 "
        "{%0,%1,%2,%3}, {%4,%5,%6,%7}, {%8,%9}, {%0,%1,%2,%3};"
        : "+f"(c[0]), "+f"(c[1]), "+f"(c[2]), "+f"(c[3])
        : "r"(a[0]), "r"(a[1]), "r"(a[2]), "r"(a[3]), "r"(b[0]), "r"(b[1]));
}

extern __shared__ char dynsmem[];

__global__ void __launch_bounds__(256, 1) gemm_kernel(float* __restrict__ out) {
    const uint32_t smem_base = smem_u32(dynsmem);
    const int tid = threadIdx.x;
    const int lane = tid & 31;
    const int warp = tid >> 5;
    const int wm = warp >> 2;        // 0..1 -> M offset 64*wm
    const int wn = warp & 3;         // 0..3 -> N offset 64*wn

    const int mBase = blockIdx.y * TILE_M;
    const int nBase = blockIdx.x * TILE_N;

    const __half* Ag = g_A + (size_t)mBase * KG;
    const __half* Bg = g_B + (size_t)nBase * KG;

    const int aRow = (lane & 7) + ((lane >> 3) & 1) * 8;
    const int aK8  = (lane >> 4) & 1;
    const int bRow = (lane & 7) + ((lane >> 4) & 1) * 8;
    const int bK8  = (lane >> 3) & 1;

    float acc[4][8][4];
    #pragma unroll
    for (int mt = 0; mt < 4; mt++)
        #pragma unroll
        for (int nt = 0; nt < 8; nt++)
            #pragma unroll
            for (int j = 0; j < 4; j++)
                acc[mt][nt][j] = 0.0f;

    // stage loader: A 1024 chunks, B 2048 chunks; 4 + 8 per thread (256 thr)
    auto load_stage = [&](int q, int buf) {
        const int k0 = q * 64;
        const uint32_t so = smem_base + buf * STAGE;
        #pragma unroll
        for (int r = 0; r < 4; r++) {
            int c = tid + 256 * r;
            int row = c >> 3, c16 = c & 7;
            cp16(so + row * ROWPB + c16 * 16,
                 Ag + (size_t)row * KG + k0 + c16 * 8);
        }
        #pragma unroll
        for (int r = 0; r < 8; r++) {
            int c = tid + 256 * r;
            int row = c >> 3, c16 = c & 7;
            cp16(so + A_ST + row * ROWPB + c16 * 16,
                 Bg + (size_t)row * KG + k0 + c16 * 8);
        }
        asm volatile("cp.async.commit_group;" ::: "memory");
    };

    load_stage(0, 0);
    load_stage(1, 1);

    for (int q = 0; q < NQG; q++) {
        if (q + 1 < NQG)
            asm volatile("cp.async.wait_group 1;" ::: "memory");
        else
            asm volatile("cp.async.wait_group 0;" ::: "memory");
        __syncthreads();
        // barrier above guarantees everyone finished reading buffer (q-1)%3,
        // which is exactly the buffer (q+2)%3 we now overwrite
        if (q + 2 < NQG)
            load_stage(q + 2, (q + 2) % 3);

        const uint32_t so = smem_base + (q % 3) * STAGE;
        const uint32_t aBase = so + (wm * 64 + aRow) * ROWPB + aK8 * 16;
        const uint32_t bBase = so + A_ST + (wn * 64 + bRow) * ROWPB + bK8 * 16;

        #pragma unroll
        for (int kk = 0; kk < 64; kk += 16) {
            uint32_t af[4][4];
            uint32_t bf[8][2];
            #pragma unroll
            for (int mt = 0; mt < 4; mt++)
                ldmx4(af[mt], aBase + mt * 16 * ROWPB + kk * 2);
            #pragma unroll
            for (int nt2 = 0; nt2 < 4; nt2++) {
                uint32_t r[4];
                ldmx4(r, bBase + nt2 * 16 * ROWPB + kk * 2);
                bf[nt2*2+0][0] = r[0]; bf[nt2*2+0][1] = r[1];
                bf[nt2*2+1][0] = r[2]; bf[nt2*2+1][1] = r[3];
            }
            #pragma unroll
            for (int mt = 0; mt < 4; mt++)
                #pragma unroll
                for (int nt = 0; nt < 8; nt++)
                    mma_f16(acc[mt][nt], af[mt], bf[nt]);
        }
    }

    // epilogue: out = acc + bias
    const int mW = mBase + wm * 64;
    const int nW = nBase + wn * 64;
    #pragma unroll
    for (int mt = 0; mt < 4; mt++) {
        #pragma unroll
        for (int nt = 0; nt < 8; nt++) {
            int row0 = mW + mt * 16 + (lane >> 2);
            int col  = nW + nt * 8 + (lane & 3) * 2;
            float b0 = g_bias[col], b1 = g_bias[col + 1];
            *(float2*)(out + (size_t)row0 * ODIM + col) =
                make_float2(acc[mt][nt][0] + b0, acc[mt][nt][1] + b1);
            *(float2*)(out + (size_t)(row0 + 8) * ODIM + col) =
                make_float2(acc[mt][nt][2] + b0, acc[mt][nt][3] + b1);
        }
    }
}

// ---------------------------------------------------------------------------
extern "C" void kernel_launch(void* const* d_in, const int* in_sizes, int n_in,
                              void* d_out, int out_size) {
    const float* x = (const float*)d_in[0];
    const float* coeffs = (const float*)d_in[1];
    float* out = (float*)d_out;

    int nb = in_sizes[0] / IDIM;   // 8192

    cudaFuncSetAttribute(gemm_kernel,
                         cudaFuncAttributeMaxDynamicSharedMemorySize, SMEM_TOTAL);

    buildT_kernel<<<nb, 256>>>(x);
    transC_kernel<<<(ODIM * (IDIM / 2) + 255) / 256, 256>>>(coeffs);
    bias_kernel<<<ODIM, 256>>>(coeffs);

    dim3 grid(ODIM / TILE_N, nb / TILE_M);   // (4, 64)
    gemm_kernel<<<grid, 256, SMEM_TOTAL>>>(out);
}

// round 14
// speedup vs baseline: 1.0796x; 1.0796x over previous
#include <cuda_runtime.h>
#include <cuda_fp16.h>
#include <cstdint>

#define IDIM 1024
#define ODIM 1024
#define NDEG 9
#define KG 8192            // GEMM K (Chebyshev j = 1..8); T0 handled as bias
#define BMAX 8192

// ---------------- device scratch (static globals: allocation-guard safe) ----
__device__ __half g_A[(size_t)BMAX * KG];   // T basis fp16, k = (j-1)*1024 + i
__device__ __half g_B[(size_t)ODIM * KG];   // coeffs fp16,  [o][k]
__device__ float g_bias[ODIM];

// ---------------------------------------------------------------------------
// Kernel 1: fused row min/max + Chebyshev basis -> fp16
// ---------------------------------------------------------------------------
__global__ void __launch_bounds__(256) buildT_kernel(const float* __restrict__ x) {
    const int b = blockIdx.x;
    const int tid = threadIdx.x;
    const float* row = x + (size_t)b * IDIM;

    float2 v[2];
    #pragma unroll
    for (int s = 0; s < 2; s++)
        v[s] = *(const float2*)(row + 2 * (tid + 256 * s));

    float mn = fminf(fminf(v[0].x, v[0].y), fminf(v[1].x, v[1].y));
    float mx = fmaxf(fmaxf(v[0].x, v[0].y), fmaxf(v[1].x, v[1].y));
    #pragma unroll
    for (int o = 16; o; o >>= 1) {
        mn = fminf(mn, __shfl_xor_sync(0xFFFFFFFFu, mn, o));
        mx = fmaxf(mx, __shfl_xor_sync(0xFFFFFFFFu, mx, o));
    }
    __shared__ float smn[8], smx[8];
    int w = tid >> 5, l = tid & 31;
    if (l == 0) { smn[w] = mn; smx[w] = mx; }
    __syncthreads();
    #pragma unroll
    for (int i = 0; i < 8; i++) { mn = fminf(mn, smn[i]); mx = fmaxf(mx, smx[i]); }
    const float sc = 2.0f / (mx - mn);

    const size_t base = (size_t)b * KG;
    #pragma unroll
    for (int s = 0; s < 2; s++) {
        int p = tid + 256 * s;
        float xa = (v[s].x - mn) * sc - 1.0f;
        float xb = (v[s].y - mn) * sc - 1.0f;
        float a0 = 1.0f, a1 = xa, b0 = 1.0f, b1 = xb;
        #pragma unroll
        for (int j = 1; j < NDEG; j++) {
            __half2 h2;
            h2.x = __float2half_rn(a1);
            h2.y = __float2half_rn(b1);
            *(__half2*)(g_A + base + (size_t)(j - 1) * IDIM + 2 * p) = h2;
            float na = 2.0f * xa * a1 - a0; a0 = a1; a1 = na;
            float nb = 2.0f * xb * b1 - b0; b0 = b1; b1 = nb;
        }
    }
}

// ---------------------------------------------------------------------------
// Kernel 2: coeffs -> B fp16 (k=(j-1)*1024+i) + bias[o] fused
// one block per o (1024 blocks, 256 thr)
// ---------------------------------------------------------------------------
__global__ void __launch_bounds__(256) transC_kernel(const float* __restrict__ c) {
    const int o = blockIdx.x;
    const int tid = threadIdx.x;
    float bsum = 0.0f;
    // each thread handles 4 i-values: i = tid + 256*s
    #pragma unroll
    for (int s = 0; s < 4; s++) {
        int i = tid + 256 * s;
        const float* src = c + ((size_t)i * ODIM + o) * NDEG;
        float v0 = src[0];
        bsum += v0;
        #pragma unroll
        for (int j = 1; j < NDEG; j++)
            g_B[(size_t)o * KG + (size_t)(j - 1) * IDIM + i] = __float2half_rn(src[j]);
    }
    // reduce bias
    #pragma unroll
    for (int w = 16; w; w >>= 1) bsum += __shfl_xor_sync(0xFFFFFFFFu, bsum, w);
    __shared__ float sh[8];
    if ((tid & 31) == 0) sh[tid >> 5] = bsum;
    __syncthreads();
    if (tid == 0) {
        float t = 0.0f;
        #pragma unroll
        for (int i = 0; i < 8; i++) t += sh[i];
        g_bias[o] = t;
    }
}

// ---------------------------------------------------------------------------
// Kernel 3: fp16 GEMM, CTA 128x128, 256 thr, warp 32x64, 3-stage, 2 CTAs/SM
// ---------------------------------------------------------------------------
#define TILE_M 128
#define TILE_N 128
#define NQG (KG / 64)               // 128 stages of 64 elems
#define ROWPB 144
#define A_ST (TILE_M * ROWPB)       // 18432
#define B_ST (TILE_N * ROWPB)       // 18432
#define STAGE (A_ST + B_ST)         // 36864
#define SMEM_TOTAL (3 * STAGE)      // 110592 per CTA -> 2 CTAs = 221184/SM

__device__ __forceinline__ uint32_t smem_u32(const void* p) {
    uint32_t a;
    asm("{ .reg .u64 t; cvta.to.shared.u64 t, %1; cvt.u32.u64 %0, t; }"
        : "=r"(a) : "l"(p));
    return a;
}
__device__ __forceinline__ void cp16(uint32_t dst, const void* src) {
    asm volatile("cp.async.cg.shared.global [%0], [%1], 16;" :: "r"(dst), "l"(src));
}
__device__ __forceinline__ void ldmx4(uint32_t* r, uint32_t addr) {
    asm volatile("ldmatrix.sync.aligned.m8n8.x4.shared.b16 {%0,%1,%2,%3}, [%4];"
                 : "=r"(r[0]), "=r"(r[1]), "=r"(r[2]), "=r"(r[3]) : "r"(addr));
}
__device__ __forceinline__ void mma_f16(float* c, const uint32_t* a, const uint32_t* b) {
    asm volatile(
        "mma.sync.aligned.m16n8k16.row.col.f32.f16.f16.f32 "
        "{%0,%1,%2,%3}, {%4,%5,%6,%7}, {%8,%9}, {%0,%1,%2,%3};"
        : "+f"(c[0]), "+f"(c[1]), "+f"(c[2]), "+f"(c[3])
        : "r"(a[0]), "r"(a[1]), "r"(a[2]), "r"(a[3]), "r"(b[0]), "r"(b[1]));
}

extern __shared__ char dynsmem[];

__global__ void __launch_bounds__(256, 2) gemm_kernel(float* __restrict__ out) {
    const uint32_t smem_base = smem_u32(dynsmem);
    const int tid = threadIdx.x;
    const int lane = tid & 31;
    const int warp = tid >> 5;
    const int wm = warp & 3;         // M band: 32*wm
    const int wn = warp >> 2;        // N band: 64*wn

    const int mBase = blockIdx.y * TILE_M;
    const int nBase = blockIdx.x * TILE_N;

    const __half* Ag = g_A + (size_t)mBase * KG;
    const __half* Bg = g_B + (size_t)nBase * KG;

    const int aRow = (lane & 7) + ((lane >> 3) & 1) * 8;
    const int aK8  = (lane >> 4) & 1;
    const int bRow = (lane & 7) + ((lane >> 4) & 1) * 8;
    const int bK8  = (lane >> 3) & 1;

    float acc[2][8][4];
    #pragma unroll
    for (int mt = 0; mt < 2; mt++)
        #pragma unroll
        for (int nt = 0; nt < 8; nt++)
            #pragma unroll
            for (int j = 0; j < 4; j++)
                acc[mt][nt][j] = 0.0f;

    // stage loader: A 1024 chunks, B 1024 chunks; 4 + 4 per thread
    auto load_stage = [&](int q, int buf) {
        const int k0 = q * 64;
        const uint32_t so = smem_base + buf * STAGE;
        #pragma unroll
        for (int r = 0; r < 4; r++) {
            int c = tid + 256 * r;
            int row = c >> 3, c16 = c & 7;
            cp16(so + row * ROWPB + c16 * 16,
                 Ag + (size_t)row * KG + k0 + c16 * 8);
        }
        #pragma unroll
        for (int r = 0; r < 4; r++) {
            int c = tid + 256 * r;
            int row = c >> 3, c16 = c & 7;
            cp16(so + A_ST + row * ROWPB + c16 * 16,
                 Bg + (size_t)row * KG + k0 + c16 * 8);
        }
        asm volatile("cp.async.commit_group;" ::: "memory");
    };

    load_stage(0, 0);
    load_stage(1, 1);

    for (int q = 0; q < NQG; q++) {
        if (q + 1 < NQG)
            asm volatile("cp.async.wait_group 1;" ::: "memory");
        else
            asm volatile("cp.async.wait_group 0;" ::: "memory");
        __syncthreads();
        // barrier guarantees buffer (q+2)%3 (== (q-1)%3) is no longer read
        if (q + 2 < NQG)
            load_stage(q + 2, (q + 2) % 3);

        const uint32_t so = smem_base + (q % 3) * STAGE;
        const uint32_t aBase = so + (wm * 32 + aRow) * ROWPB + aK8 * 16;
        const uint32_t bBase = so + A_ST + (wn * 64 + bRow) * ROWPB + bK8 * 16;

        #pragma unroll
        for (int kk = 0; kk < 64; kk += 16) {
            uint32_t af[2][4];
            uint32_t bf[8][2];
            #pragma unroll
            for (int mt = 0; mt < 2; mt++)
                ldmx4(af[mt], aBase + mt * 16 * ROWPB + kk * 2);
            #pragma unroll
            for (int nt2 = 0; nt2 < 4; nt2++) {
                uint32_t r[4];
                ldmx4(r, bBase + nt2 * 16 * ROWPB + kk * 2);
                bf[nt2*2+0][0] = r[0]; bf[nt2*2+0][1] = r[1];
                bf[nt2*2+1][0] = r[2]; bf[nt2*2+1][1] = r[3];
            }
            #pragma unroll
            for (int mt = 0; mt < 2; mt++)
                #pragma unroll
                for (int nt = 0; nt < 8; nt++)
                    mma_f16(acc[mt][nt], af[mt], bf[nt]);
        }
    }

    // epilogue: out = acc + bias
    const int mW = mBase + wm * 32;
    const int nW = nBase + wn * 64;
    #pragma unroll
    for (int mt = 0; mt < 2; mt++) {
        #pragma unroll
        for (int nt = 0; nt < 8; nt++) {
            int row0 = mW + mt * 16 + (lane >> 2);
            int col  = nW + nt * 8 + (lane & 3) * 2;
            float b0 = g_bias[col], b1 = g_bias[col + 1];
            *(float2*)(out + (size_t)row0 * ODIM + col) =
                make_float2(acc[mt][nt][0] + b0, acc[mt][nt][1] + b1);
            *(float2*)(out + (size_t)(row0 + 8) * ODIM + col) =
                make_float2(acc[mt][nt][2] + b0, acc[mt][nt][3] + b1);
        }
    }
}

// ---------------------------------------------------------------------------
extern "C" void kernel_launch(void* const* d_in, const int* in_sizes, int n_in,
                              void* d_out, int out_size) {
    const float* x = (const float*)d_in[0];
    const float* coeffs = (const float*)d_in[1];
    float* out = (float*)d_out;

    int nb = in_sizes[0] / IDIM;   // 8192

    cudaFuncSetAttribute(gemm_kernel,
                         cudaFuncAttributeMaxDynamicSharedMemorySize, SMEM_TOTAL);

    buildT_kernel<<<nb, 256>>>(x);
    transC_kernel<<<ODIM, 256>>>(coeffs);

    dim3 grid(ODIM / TILE_N, nb / TILE_M);   // (8, 64) = 512 CTAs
    gemm_kernel<<<grid, 256, SMEM_TOTAL>>>(out);
}